// round 12
// baseline (speedup 1.0000x reference)
#include <cuda_runtime.h>

// Problem constants
#define KK 4
#define MM 32
#define DD 2048
#define TT 128
#define NTHREADS 1024
#define NTILES 2048        // 128 km * 16 t-blocks of 8 t-columns

typedef unsigned long long u64;

// smem: 16 t-buffers (8 per half) * 2050 floats + 4 tables * 1024 u64
#define XSF 2050                    // floats per t-buffer (64*32 + 2)
#define XCH_U64 16400               // 16*2050/2
#define T1O (XCH_U64)
#define T3O (T1O + 1024)
#define T2O (T3O + 1024)
#define TBO (T2O + 1024)
#define SMEM_U64 (TBO + 1024)       // 20496
#define SMEM_BYTES (SMEM_U64 * 8)   // 163968

#define HNORM 0.022097086912079608f   // 1/sqrt(2048), folded per diagonal

// ---- packed f32x2 helpers (sm_103a) ----
__device__ __forceinline__ u64 addx2(u64 a, u64 b) {
    u64 r; asm("add.rn.f32x2 %0,%1,%2;" : "=l"(r) : "l"(a), "l"(b)); return r;
}
__device__ __forceinline__ u64 subx2(u64 a, u64 b) {
    u64 r; asm("sub.rn.f32x2 %0,%1,%2;" : "=l"(r) : "l"(a), "l"(b)); return r;
}
__device__ __forceinline__ u64 mulx2(u64 a, u64 b) {
    u64 r; asm("mul.rn.f32x2 %0,%1,%2;" : "=l"(r) : "l"(a), "l"(b)); return r;
}
__device__ __forceinline__ u64 pk(float lo, float hi) {
    u64 r; asm("mov.b64 %0,{%1,%2};" : "=l"(r) : "f"(lo), "f"(hi)); return r;
}
__device__ __forceinline__ void upk(float& lo, float& hi, u64 v) {
    asm("mov.b64 {%0,%1},%2;" : "=f"(lo), "=f"(hi) : "l"(v));
}

#define BFLY(A, B) { u64 _a = (A), _b = (B); (A) = addx2(_a, _b); (B) = subx2(_a, _b); }

// 4 local stages over 16-reg array (reg-index bits 0..3)
#define LOCAL4(y) \
    { _Pragma("unroll") for (int s = 1; s < 16; s <<= 1) { \
        _Pragma("unroll") for (int j = 0; j < 16; ++j) \
            if ((j & s) == 0) BFLY(y[j], y[j | s]); } }

// cross-lane stage over q = lane bit 3 (phase-1 d0)
#define CROSS8(y, q) \
    { _Pragma("unroll") for (int i = 0; i < 16; ++i) { \
        u64 _o = __shfl_xor_sync(0xffffffffu, y[i], 8); \
        y[i] = (q) ? subx2(_o, y[i]) : addx2(y[i], _o); } }

// intra-pack stage
#define INTRA(y) \
    { _Pragma("unroll") for (int i = 0; i < 16; ++i) { \
        float _lo, _hi; upk(_lo, _hi, y[i]); \
        y[i] = pk(_lo + _hi, _lo - _hi); } }

// half-domain barrier (512 threads, ids 1/2)
#define HBAR(id) asm volatile("bar.sync %0, 512;" :: "r"(id) : "memory")

__global__ __launch_bounds__(NTHREADS, 1)
void spinner_main_kernel(const float* __restrict__ z,
                         const float* __restrict__ d1,
                         const float* __restrict__ d2,
                         const float* __restrict__ d3,
                         const float* __restrict__ bia,
                         const float* __restrict__ sldj_in,
                         float* __restrict__ out)
{
    extern __shared__ u64 sm[];
    const int tid = threadIdx.x;
    const int bid = blockIdx.x;

    // ---- block 0: sldj ----
    if (bid == 0) {
        float* red = (float*)sm;
        float s = 0.f;
        #pragma unroll
        for (int r = 0; r < 2; ++r) {
            int i = tid + r * NTHREADS;
            s += logf(fabsf(d1[i])) + logf(fabsf(d2[i])) + logf(fabsf(d3[i]));
        }
        red[tid] = s;
        __syncthreads();
        #pragma unroll
        for (int w = 512; w > 0; w >>= 1) {
            if (tid < w) red[tid] += red[tid + w];
            __syncthreads();
        }
        float ld = red[0];
        if (tid < KK * MM)
            out[(size_t)KK * MM * DD * TT + tid] = sldj_in[tid] + ld;
        return;
    }

    float* xcf = (float*)sm;     // exchange, float-granular

    // decode: half hf (warps 0-15 / 16-31); per-half 512-thread pipeline
    const int hf  = tid >> 9;
    const int t8  = tid & 7;                 // t within half's 8-t tile
    const int q   = (tid >> 3) & 1;          // phase-1 d0 / phase-2 dlow bit0
    const int ub  = (tid >> 4) & 1;
    const int w   = (tid >> 5) & 15;         // warp index within half
    const int u   = w + 16 * ub;             // phase-1 d-high (d6..d10)
    const int dlow = 4 * w + 2 * ub + q;     // phase-2 d-low (d0..d5)

    const int tile = 2 * (bid - 1) + hf;
    const int km = tile >> 4;
    const int t0 = (tile & 15) * 8;
    const int tcol = t0 + t8;

    const float* zin = z + (size_t)km * (DD * TT) + tcol;
    u64 y[16];

    // ---- PREFETCH raw z (phase-1: rows u*64 + 2i + q, pack +32) ----
    {
        const float* zrow = zin + (size_t)(u * 64 + q) * TT;
        #pragma unroll
        for (int i = 0; i < 16; ++i)
            y[i] = pk(zrow[(size_t)(2 * i) * TT], zrow[(size_t)(2 * i + 32) * TT]);
    }

    // ---- stage tables (full CTA; overlaps z-load latency) ----
    {
        int e = tid;
        // T1/T3: entry e = u_*32 + s holds value for dl = s ^ (2*(u_>>4))
        int u_ = e >> 5, s_ = e & 31;
        int dl = s_ ^ ((u_ >> 4) << 1);
        int d  = u_ * 64 + dl;
        sm[T1O + e] = pk(d1[d] * HNORM, d1[d + 32] * HNORM);
        sm[T3O + e] = pk(d3[d] * HNORM, d3[d + 32] * HNORM);
        // T2/TB: entry e = dlow_*16 + mm holds value for m = mm ^ (dlow_&3)
        int dlow_ = e >> 4, mm = e & 15;
        int m  = mm ^ (dlow_ & 3);
        int hh = (m & 7) + ((m >> 3) << 4);  // h bits: m0..2 -> h0..2, m3 -> h4
        int dd = hh * 64 + dlow_;
        sm[T2O + e] = pk(d2[dd] * HNORM, d2[dd + 512] * HNORM);
        sm[TBO + e] = pk(bia[dd], bia[dd + 512]);
    }
    __syncthreads();

    const int barid = 1 + hf;
    const int sc1 = ub << 1;                                     // T1/T3 scramble
    const int sq  = (16 * ub + 2 * (w & 7) + ((w >> 3) & 1)) ^ q; // sigma0(u)^q
    float* xt = xcf + (size_t)(hf * 8 + t8) * XSF;
    float* xr = xt + dlow * 32;
    const int sc2 = dlow & 3;                                    // T2/TB scramble

    // ---- d1 scale ----
    #pragma unroll
    for (int i = 0; i < 16; ++i)
        y[i] = mulx2(y[i], sm[T1O + u * 32 + ((2 * i + q) ^ sc1)]);

    // ---- FWHT #1 low (d0..d5) ----
    CROSS8(y, q); LOCAL4(y); INTRA(y);

    // E1-write: rows 2i+q and 2i+q+32 at column slot sq
    #pragma unroll
    for (int i = 0; i < 16; ++i) {
        float lo, hi; upk(lo, hi, y[i]);
        xt[(2 * i + q) * 32 + sq]      = lo;
        xt[(2 * i + q + 32) * 32 + sq] = hi;
    }
    HBAR(barid);
    // E1-read: float2 pairs (h, h+8) at own dlow; parity (=q) swaps halves
    #pragma unroll
    for (int m = 0; m < 16; ++m) {
        int off = 16 * (m >> 3) + 2 * (m & 7);
        float2 v = *(const float2*)(xr + off);
        y[m] = q ? pk(v.y, v.x) : pk(v.x, v.y);
    }

    // ---- FWHT #1 high (d6..d10): regs m + pack d9 ----
    LOCAL4(y); INTRA(y);

    // ---- d2 scale ----
    #pragma unroll
    for (int m = 0; m < 16; ++m)
        y[m] = mulx2(y[m], sm[T2O + dlow * 16 + (m ^ sc2)]);

    // ---- FWHT #2 high ----
    INTRA(y); LOCAL4(y);

    // E2-write: STS.64 back to own E1-read slots (no pre-barrier needed)
    #pragma unroll
    for (int m = 0; m < 16; ++m) {
        int off = 16 * (m >> 3) + 2 * (m & 7);
        u64 v = y[m];
        if (q) v = (v >> 32) | (v << 32);
        *(u64*)(xr + off) = v;
    }
    HBAR(barid);
    // E2-read: phase-1 pattern (two LDS.32 per reg)
    #pragma unroll
    for (int i = 0; i < 16; ++i) {
        float lo = xt[(2 * i + q) * 32 + sq];
        float hi = xt[(2 * i + q + 32) * 32 + sq];
        y[i] = pk(lo, hi);
    }

    // ---- FWHT #2 low ----
    INTRA(y); LOCAL4(y); CROSS8(y, q);

    // ---- d3 scale ----
    #pragma unroll
    for (int i = 0; i < 16; ++i)
        y[i] = mulx2(y[i], sm[T3O + u * 32 + ((2 * i + q) ^ sc1)]);

    // ---- FWHT #3 low ----
    CROSS8(y, q); LOCAL4(y); INTRA(y);

    // E3-write (own E2-read slots: no pre-barrier)
    #pragma unroll
    for (int i = 0; i < 16; ++i) {
        float lo, hi; upk(lo, hi, y[i]);
        xt[(2 * i + q) * 32 + sq]      = lo;
        xt[(2 * i + q + 32) * 32 + sq] = hi;
    }
    HBAR(barid);
    // E3-read
    #pragma unroll
    for (int m = 0; m < 16; ++m) {
        int off = 16 * (m >> 3) + 2 * (m & 7);
        float2 v = *(const float2*)(xr + off);
        y[m] = q ? pk(v.y, v.x) : pk(v.x, v.y);
    }

    // ---- FWHT #3 high ----
    LOCAL4(y); INTRA(y);

    // ---- bias + store (rows h*64+dlow and h*64+512+dlow) ----
    {
        float* zo = out + (size_t)km * (DD * TT) + (size_t)dlow * TT + tcol;
        #pragma unroll
        for (int m = 0; m < 16; ++m) {
            u64 r = addx2(y[m], sm[TBO + dlow * 16 + (m ^ sc2)]);
            float lo, hi; upk(lo, hi, r);
            int hh = (m & 7) + ((m >> 3) << 4);
            zo[(size_t)(hh * 64) * TT]         = lo;
            zo[(size_t)(hh * 64 + 512) * TT]   = hi;
        }
    }
}

extern "C" void kernel_launch(void* const* d_in, const int* in_sizes, int n_in,
                              void* d_out, int out_size)
{
    (void)in_sizes; (void)n_in; (void)out_size;
    const float* z    = (const float*)d_in[0];
    const float* d1   = (const float*)d_in[1];
    const float* d2   = (const float*)d_in[2];
    const float* d3   = (const float*)d_in[3];
    const float* bia  = (const float*)d_in[4];
    const float* sldj = (const float*)d_in[5];
    float* out = (float*)d_out;

    cudaFuncSetAttribute(spinner_main_kernel,
                         cudaFuncAttributeMaxDynamicSharedMemorySize, SMEM_BYTES);

    // grid: 1 sldj block + 1024 dual-tile blocks (2 tiles per CTA, one per half)
    spinner_main_kernel<<<NTILES / 2 + 1, NTHREADS, SMEM_BYTES>>>(
        z, d1, d2, d3, bia, sldj, out);
}

// round 13
// speedup vs baseline: 1.1085x; 1.1085x over previous
#include <cuda_runtime.h>

// Problem constants
#define KK 4
#define MM 32
#define DD 2048
#define TT 128
#define TTILE 16          // t-columns per CTA (64B of each 128B line)
#define NTHREADS 1024
#define NTILES 1024       // 128 km * 8 t-blocks

typedef unsigned long long u64;

// smem (u64 units):
//  xch: 16 t-buffers * 1025 u64 (2050 floats, t-stride == 2 banks)
//  T1/T3: phase-1 packed (d, d+32); T2/TB: phase-2 packed (d, d+1024), q-split
#define XSU 1025
#define XCH_U64 (16 * XSU)         // 16400
#define T1O (XCH_U64)
#define T3O (T1O + 1024)
#define T2O (T3O + 1024)
#define TBO (T2O + 1200)
#define SMEM_U64 (TBO + 1200)      // 20848
#define SMEM_BYTES (SMEM_U64 * 8)  // 166784

#define HNORM 0.022097086912079608f   // 1/sqrt(2048), folded per diagonal

// ---- packed f32x2 helpers (sm_103a) ----
__device__ __forceinline__ u64 addx2(u64 a, u64 b) {
    u64 r; asm("add.rn.f32x2 %0,%1,%2;" : "=l"(r) : "l"(a), "l"(b)); return r;
}
__device__ __forceinline__ u64 subx2(u64 a, u64 b) {
    u64 r; asm("sub.rn.f32x2 %0,%1,%2;" : "=l"(r) : "l"(a), "l"(b)); return r;
}
__device__ __forceinline__ u64 mulx2(u64 a, u64 b) {
    u64 r; asm("mul.rn.f32x2 %0,%1,%2;" : "=l"(r) : "l"(a), "l"(b)); return r;
}
__device__ __forceinline__ u64 pk(float lo, float hi) {
    u64 r; asm("mov.b64 %0,{%1,%2};" : "=l"(r) : "f"(lo), "f"(hi)); return r;
}
__device__ __forceinline__ void upk(float& lo, float& hi, u64 v) {
    asm("mov.b64 {%0,%1},%2;" : "=f"(lo), "=f"(hi) : "l"(v));
}

#define BFLY(A, B) { u64 _a = (A), _b = (B); (A) = addx2(_a, _b); (B) = subx2(_a, _b); }

// 4 local stages over 16-reg array (reg-index bits 0..3)
#define LOCAL4(y) \
    { _Pragma("unroll") for (int s = 1; s < 16; s <<= 1) { \
        _Pragma("unroll") for (int j = 0; j < 16; ++j) \
            if ((j & s) == 0) BFLY(y[j], y[j | s]); } }

// cross-thread stage (d0 bit = lane bit 4), phase-1 only
#define CROSS(y, q) \
    { _Pragma("unroll") for (int i = 0; i < 16; ++i) { \
        u64 _o = __shfl_xor_sync(0xffffffffu, y[i], 16); \
        y[i] = (q) ? subx2(_o, y[i]) : addx2(y[i], _o); } }

// intra-register stage (pack-bit butterfly)
#define INTRA(y) \
    { _Pragma("unroll") for (int i = 0; i < 16; ++i) { \
        float _lo, _hi; upk(_lo, _hi, y[i]); \
        y[i] = pk(_lo + _hi, _lo - _hi); } }

__global__ __launch_bounds__(NTHREADS, 1)
void spinner_main_kernel(const float* __restrict__ z,
                         const float* __restrict__ d1,
                         const float* __restrict__ d2,
                         const float* __restrict__ d3,
                         const float* __restrict__ bia,
                         const float* __restrict__ sldj_in,
                         float* __restrict__ out)
{
    extern __shared__ u64 sm[];
    const int tid = threadIdx.x;
    const int bid = blockIdx.x;

    // ---- block 0: sldj ----
    if (bid == 0) {
        float* red = (float*)sm;
        float s = 0.f;
        #pragma unroll
        for (int r = 0; r < 2; ++r) {
            int i = tid + r * NTHREADS;
            s += logf(fabsf(d1[i])) + logf(fabsf(d2[i])) + logf(fabsf(d3[i]));
        }
        red[tid] = s;
        __syncthreads();
        #pragma unroll
        for (int w = 512; w > 0; w >>= 1) {
            if (tid < w) red[tid] += red[tid + w];
            __syncthreads();
        }
        float ld = red[0];
        if (tid < KK * MM)
            out[(size_t)KK * MM * DD * TT + tid] = sldj_in[tid] + ld;
        return;
    }

    float* xcf = (float*)sm;                 // exchange, float-granular

    const int tile = bid - 1;
    const int km = tile >> 3;
    const int t0 = (tile & 7) * TTILE;
    const int t  = tid & 15;
    const int q  = (tid >> 4) & 1;
    const int u  = tid >> 5;                 // 0..31

    const float* zin = z + (size_t)km * (DD * TT) + (t0 + t);
    u64 y[16];

    // ---- PREFETCH raw z (phase-1: h=u, dlow = 2i+q packed with +32) ----
    #pragma unroll
    for (int i = 0; i < 16; ++i) {
        int dlo = u * 64 + 2 * i + q;
        y[i] = pk(zin[(size_t)dlo * TT], zin[(size_t)(dlo + 32) * TT]);
    }

    // ---- stage scale tables (overlaps z-load latency) ----
    {
        int c = tid >> 5, p = tid & 31;
        int d = c * 64 + p;
        sm[T1O + tid] = pk(d1[d] * HNORM, d1[d + 32] * HNORM);
        sm[T3O + tid] = pk(d3[d] * HNORM, d3[d + 32] * HNORM);
        int q_ = tid >> 9, r_ = tid & 511;
        int u_ = r_ >> 4, k_ = r_ & 15;
        int dl = u_ + 32 * q_;
        sm[T2O + q_ * 600 + r_] = pk(d2[k_ * 64 + dl] * HNORM,
                                     d2[(k_ + 16) * 64 + dl] * HNORM);
        sm[TBO + q_ * 600 + r_] = pk(bia[k_ * 64 + dl],
                                     bia[(k_ + 16) * 64 + dl]);
    }
    __syncthreads();

    // ---- d1 scale ----
    #pragma unroll
    for (int i = 0; i < 16; ++i)
        y[i] = mulx2(y[i], sm[T1O + u * 32 + 2 * i + q]);

    // ---- FWHT #1 low (d0..d5): CROSS(d0) + LOCAL4(d1-d4) + INTRA(d5) ----
    CROSS(y, q); LOCAL4(y); INTRA(y);

    // exchange addressing:
    //   slot(row r, h) = r*32 + ( sigma0(h) ^ (r&1) ^ ((r>>5)&1) )
    float* xt = xcf + t * 2050;
    const int sq   = (2 * (u & 15) + (u >> 4)) ^ q;  // phase-1 lo-row column
    const int sq1  = sq ^ 1;                         // phase-1 hi-row column
    const int dlow = u + 32 * q;                     // phase-2 owned d-low
    const int pq   = (u & 1) ^ q;                    // (r&1)^(r>>5&1) for r=dlow
    float* xr  = xt + dlow * 32;
    float* blo = xr + pq;                            // columns for h = k
    float* bhi = xr + 1 - pq;                        // columns for h = k+16

    // E1-write: rows (2i+q) at col sq, rows (2i+q+32) at col sq^1
    #pragma unroll
    for (int i = 0; i < 16; ++i) {
        float lo, hi; upk(lo, hi, y[i]);
        xt[(2 * i + q) * 32 + sq]       = lo;
        xt[(2 * i + q + 32) * 32 + sq1] = hi;
    }
    __syncthreads();
    // E1-read: conflict-free LDS.32 pairs (h=k at blo, h=k+16 at bhi)
    #pragma unroll
    for (int k = 0; k < 16; ++k)
        y[k] = pk(blo[2 * k], bhi[2 * k]);

    // ---- FWHT #1 high (d6..d10): LOCAL4(d6-d9) + INTRA(d10) ----
    LOCAL4(y); INTRA(y);

    // ---- d2 scale (phase-2 pack (d, d+1024)) ----
    {
        const u64* t2 = sm + T2O + q * 600 + u * 16;
        #pragma unroll
        for (int k = 0; k < 16; ++k) y[k] = mulx2(y[k], t2[k]);
    }

    // ---- FWHT #2 high ----
    INTRA(y); LOCAL4(y);

    // E2-write: back to own E1-read slots (conflict-free .32; no pre-sync)
    #pragma unroll
    for (int k = 0; k < 16; ++k) {
        float lo, hi; upk(lo, hi, y[k]);
        blo[2 * k] = lo;
        bhi[2 * k] = hi;
    }
    __syncthreads();
    // E2-read: phase-1 pattern (two LDS.32 per reg)
    #pragma unroll
    for (int i = 0; i < 16; ++i) {
        float lo = xt[(2 * i + q) * 32 + sq];
        float hi = xt[(2 * i + q + 32) * 32 + sq1];
        y[i] = pk(lo, hi);
    }

    // ---- FWHT #2 low ----
    INTRA(y); LOCAL4(y); CROSS(y, q);

    // ---- d3 scale ----
    #pragma unroll
    for (int i = 0; i < 16; ++i)
        y[i] = mulx2(y[i], sm[T3O + u * 32 + 2 * i + q]);

    // ---- FWHT #3 low ----
    CROSS(y, q); LOCAL4(y); INTRA(y);

    // E3-write (own E2-read slots: no pre-sync)
    #pragma unroll
    for (int i = 0; i < 16; ++i) {
        float lo, hi; upk(lo, hi, y[i]);
        xt[(2 * i + q) * 32 + sq]       = lo;
        xt[(2 * i + q + 32) * 32 + sq1] = hi;
    }
    __syncthreads();
    // E3-read
    #pragma unroll
    for (int k = 0; k < 16; ++k)
        y[k] = pk(blo[2 * k], bhi[2 * k]);

    // ---- FWHT #3 high ----
    LOCAL4(y); INTRA(y);

    // ---- bias + store (rows k*64+dlow and (k+16)*64+dlow) ----
    {
        float* zout = out + (size_t)km * (DD * TT) + (t0 + t);
        const u64* tb = sm + TBO + q * 600 + u * 16;
        #pragma unroll
        for (int k = 0; k < 16; ++k) {
            u64 r_ = addx2(y[k], tb[k]);
            float lo, hi; upk(lo, hi, r_);
            zout[(size_t)(k * 64 + dlow) * TT]        = lo;
            zout[(size_t)((k + 16) * 64 + dlow) * TT] = hi;
        }
    }
}

extern "C" void kernel_launch(void* const* d_in, const int* in_sizes, int n_in,
                              void* d_out, int out_size)
{
    (void)in_sizes; (void)n_in; (void)out_size;
    const float* z    = (const float*)d_in[0];
    const float* d1   = (const float*)d_in[1];
    const float* d2   = (const float*)d_in[2];
    const float* d3   = (const float*)d_in[3];
    const float* bia  = (const float*)d_in[4];
    const float* sldj = (const float*)d_in[5];
    float* out = (float*)d_out;

    cudaFuncSetAttribute(spinner_main_kernel,
                         cudaFuncAttributeMaxDynamicSharedMemorySize, SMEM_BYTES);

    // grid: 1 sldj block + 1024 tile blocks
    spinner_main_kernel<<<NTILES + 1, NTHREADS, SMEM_BYTES>>>(
        z, d1, d2, d3, bia, sldj, out);
}

// round 14
// speedup vs baseline: 1.1468x; 1.0346x over previous
#include <cuda_runtime.h>

// Problem constants
#define KK 4
#define MM 32
#define DD 2048
#define TT 128
#define TTILE 16          // t-columns per CTA (64B of each 128B line)
#define NTHREADS 1024
#define NTILES 1024       // 128 km * 8 t-blocks

typedef unsigned long long u64;

// smem (u64 units):
//  xch: 16 t-buffers * 1025 u64 (2050 floats, odd u64 stride -> conflict-free)
//  T3: phase-1 packed (d, d+32); T2/TB: phase-2 packed (d, d+1024), q-split
#define XSU 1025
#define XCH_U64 (16 * XSU)         // 16400
#define T3O (XCH_U64)
#define T2O (T3O + 1024)
#define TBO (T2O + 1200)
#define SMEM_U64 (TBO + 1200)      // 19824
#define SMEM_BYTES (SMEM_U64 * 8)  // 158592

#define HNORM 0.022097086912079608f     // 1/sqrt(2048)
#define HN3 (HNORM * HNORM * HNORM)     // folded once into d2 staging

// ---- packed f32x2 helpers (sm_103a) ----
__device__ __forceinline__ u64 addx2(u64 a, u64 b) {
    u64 r; asm("add.rn.f32x2 %0,%1,%2;" : "=l"(r) : "l"(a), "l"(b)); return r;
}
__device__ __forceinline__ u64 subx2(u64 a, u64 b) {
    u64 r; asm("sub.rn.f32x2 %0,%1,%2;" : "=l"(r) : "l"(a), "l"(b)); return r;
}
__device__ __forceinline__ u64 mulx2(u64 a, u64 b) {
    u64 r; asm("mul.rn.f32x2 %0,%1,%2;" : "=l"(r) : "l"(a), "l"(b)); return r;
}
__device__ __forceinline__ u64 pk(float lo, float hi) {
    u64 r; asm("mov.b64 %0,{%1,%2};" : "=l"(r) : "f"(lo), "f"(hi)); return r;
}
__device__ __forceinline__ void upk(float& lo, float& hi, u64 v) {
    asm("mov.b64 {%0,%1},%2;" : "=f"(lo), "=f"(hi) : "l"(v));
}

#define BFLY(A, B) { u64 _a = (A), _b = (B); (A) = addx2(_a, _b); (B) = subx2(_a, _b); }

// 4 local stages over 16-reg array (reg-index bits 0..3)
#define LOCAL4(y) \
    { _Pragma("unroll") for (int s = 1; s < 16; s <<= 1) { \
        _Pragma("unroll") for (int j = 0; j < 16; ++j) \
            if ((j & s) == 0) BFLY(y[j], y[j | s]); } }

// cross-thread stage (d0 bit = lane bit 4), phase-1 only
#define CROSS(y, q) \
    { _Pragma("unroll") for (int i = 0; i < 16; ++i) { \
        u64 _o = __shfl_xor_sync(0xffffffffu, y[i], 16); \
        y[i] = (q) ? subx2(_o, y[i]) : addx2(y[i], _o); } }

// intra-register stage (pack-bit butterfly)
#define INTRA(y) \
    { _Pragma("unroll") for (int i = 0; i < 16; ++i) { \
        float _lo, _hi; upk(_lo, _hi, y[i]); \
        y[i] = pk(_lo + _hi, _lo - _hi); } }

__global__ __launch_bounds__(NTHREADS, 1)
void spinner_main_kernel(const float* __restrict__ z,
                         const float* __restrict__ d1,
                         const float* __restrict__ d2,
                         const float* __restrict__ d3,
                         const float* __restrict__ bia,
                         const float* __restrict__ sldj_in,
                         float* __restrict__ out)
{
    extern __shared__ u64 sm[];
    const int tid = threadIdx.x;
    const int bid = blockIdx.x;

    // ---- block 0: sldj ----
    if (bid == 0) {
        float* red = (float*)sm;
        float s = 0.f;
        #pragma unroll
        for (int r = 0; r < 2; ++r) {
            int i = tid + r * NTHREADS;
            s += logf(fabsf(d1[i])) + logf(fabsf(d2[i])) + logf(fabsf(d3[i]));
        }
        red[tid] = s;
        __syncthreads();
        #pragma unroll
        for (int w = 512; w > 0; w >>= 1) {
            if (tid < w) red[tid] += red[tid + w];
            __syncthreads();
        }
        float ld = red[0];
        if (tid < KK * MM)
            out[(size_t)KK * MM * DD * TT + tid] = sldj_in[tid] + ld;
        return;
    }

    float* xcf = (float*)sm;                 // exchange, float-granular

    const int tile = bid - 1;
    const int km = tile >> 3;
    const int t0 = (tile & 7) * TTILE;
    const int t  = tid & 15;
    const int q  = (tid >> 4) & 1;
    const int u  = tid >> 5;                 // 0..31

    const float* zin = z + (size_t)km * (DD * TT) + (t0 + t);
    u64 y[16];

    // ---- load z (streaming) + d1 scale from global (warp-broadcast, L2-hot) ----
    #pragma unroll
    for (int i = 0; i < 16; ++i) {
        int dlo = u * 64 + 2 * i + q;
        u64 zp = pk(__ldcs(zin + (size_t)dlo * TT),
                    __ldcs(zin + (size_t)(dlo + 32) * TT));
        u64 sp = pk(__ldg(d1 + dlo), __ldg(d1 + dlo + 32));
        y[i] = mulx2(zp, sp);
    }

    // ---- stage scale tables (no barrier needed: first use is after E1's bar) ----
    {
        int c = tid >> 5, p = tid & 31;
        int d = c * 64 + p;
        sm[T3O + tid] = pk(d3[d], d3[d + 32]);
        int q_ = tid >> 9, r_ = tid & 511;
        int u_ = r_ >> 4, k_ = r_ & 15;
        int dl = u_ + 32 * q_;
        sm[T2O + q_ * 600 + r_] = pk(d2[k_ * 64 + dl] * HN3,
                                     d2[(k_ + 16) * 64 + dl] * HN3);
        sm[TBO + q_ * 600 + r_] = pk(bia[k_ * 64 + dl],
                                     bia[(k_ + 16) * 64 + dl]);
    }

    // ---- FWHT #1 low (d0..d5): CROSS(d0) + LOCAL4(d1-d4) + INTRA(d5) ----
    CROSS(y, q); LOCAL4(y); INTRA(y);

    // exchange addressing
    float* xt = xcf + t * 2050;
    const int sq   = (2 * (u & 15) + (u >> 4)) ^ q;  // sigma0(u) ^ parity(dlow)
    const int dlow = u + 32 * q;                     // phase-2 owned d-low
    const int par  = u & 1;                          // parity(dlow) in phase-2
    float* xr = xt + dlow * 32;

    // E1-write: float (dlow=2i+q, h=u) and (dlow+32, h=u)
    #pragma unroll
    for (int i = 0; i < 16; ++i) {
        float lo, hi; upk(lo, hi, y[i]);
        xt[(2 * i + q) * 32 + sq]        = lo;
        xt[(2 * i + q + 32) * 32 + sq]   = hi;
    }
    __syncthreads();
    // E1-read: LDS.64 pairs (h=k, h=k+16) at own dlow (parity swap)
    #pragma unroll
    for (int k = 0; k < 16; ++k) {
        float2 v = *(const float2*)(xr + 2 * k);
        y[k] = par ? pk(v.y, v.x) : pk(v.x, v.y);
    }

    // ---- FWHT #1 high (d6..d10): LOCAL4(d6-d9) + INTRA(d10) ----
    LOCAL4(y); INTRA(y);

    // ---- d2 scale (phase-2 pack (d, d+1024)); carries HNORM^3 ----
    {
        const u64* t2 = sm + T2O + q * 600 + u * 16;
        #pragma unroll
        for (int k = 0; k < 16; ++k) y[k] = mulx2(y[k], t2[k]);
    }

    // ---- FWHT #2 high ----
    INTRA(y); LOCAL4(y);

    // E2-write: STS.64 back to own E1-read slots (no pre-sync needed)
    #pragma unroll
    for (int k = 0; k < 16; ++k) {
        u64 v = y[k];
        if (par) v = (v >> 32) | (v << 32);
        *(u64*)(xr + 2 * k) = v;
    }
    __syncthreads();
    // E2-read: two LDS.32 per reg (phase-1 pattern)
    #pragma unroll
    for (int i = 0; i < 16; ++i) {
        float lo = xt[(2 * i + q) * 32 + sq];
        float hi = xt[(2 * i + q + 32) * 32 + sq];
        y[i] = pk(lo, hi);
    }

    // ---- FWHT #2 low ----
    INTRA(y); LOCAL4(y); CROSS(y, q);

    // ---- d3 scale ----
    #pragma unroll
    for (int i = 0; i < 16; ++i)
        y[i] = mulx2(y[i], sm[T3O + u * 32 + 2 * i + q]);

    // ---- FWHT #3 low ----
    CROSS(y, q); LOCAL4(y); INTRA(y);

    // E3-write (own E2-read slots: no pre-sync)
    #pragma unroll
    for (int i = 0; i < 16; ++i) {
        float lo, hi; upk(lo, hi, y[i]);
        xt[(2 * i + q) * 32 + sq]        = lo;
        xt[(2 * i + q + 32) * 32 + sq]   = hi;
    }
    __syncthreads();
    // E3-read
    #pragma unroll
    for (int k = 0; k < 16; ++k) {
        float2 v = *(const float2*)(xr + 2 * k);
        y[k] = par ? pk(v.y, v.x) : pk(v.x, v.y);
    }

    // ---- FWHT #3 high ----
    LOCAL4(y); INTRA(y);

    // ---- bias + store (streaming; rows k*64+dlow and (k+16)*64+dlow) ----
    {
        float* zout = out + (size_t)km * (DD * TT) + (t0 + t);
        const u64* tb = sm + TBO + q * 600 + u * 16;
        #pragma unroll
        for (int k = 0; k < 16; ++k) {
            u64 r_ = addx2(y[k], tb[k]);
            float lo, hi; upk(lo, hi, r_);
            __stcs(zout + (size_t)(k * 64 + dlow) * TT, lo);
            __stcs(zout + (size_t)((k + 16) * 64 + dlow) * TT, hi);
        }
    }
}

extern "C" void kernel_launch(void* const* d_in, const int* in_sizes, int n_in,
                              void* d_out, int out_size)
{
    (void)in_sizes; (void)n_in; (void)out_size;
    const float* z    = (const float*)d_in[0];
    const float* d1   = (const float*)d_in[1];
    const float* d2   = (const float*)d_in[2];
    const float* d3   = (const float*)d_in[3];
    const float* bia  = (const float*)d_in[4];
    const float* sldj = (const float*)d_in[5];
    float* out = (float*)d_out;

    cudaFuncSetAttribute(spinner_main_kernel,
                         cudaFuncAttributeMaxDynamicSharedMemorySize, SMEM_BYTES);

    // grid: 1 sldj block + 1024 tile blocks
    spinner_main_kernel<<<NTILES + 1, NTHREADS, SMEM_BYTES>>>(
        z, d1, d2, d3, bia, sldj, out);
}